// round 11
// baseline (speedup 1.0000x reference)
#include <cuda_runtime.h>
#include <cuda_fp16.h>
#include <cuda_bf16.h>

#define NN 50000
#define DD 128
#define CAP 96           // bucket capacity per node; P(Poisson(32) >= 96) ~ 1e-18

typedef unsigned int uint;

// Scratch (no allocation allowed). g_edges is zero-initialized at module load;
// slots beyond each node's degree are NEVER written, so they stay
// (src=0, w=half2(0,0)) forever -> safe zero-weight padding for rounded-up
// gather waves (row 0 is L1-hot; still costs L1 wavefronts, so padding is
// minimized with an 8-edge tail wave).
__device__ __half g_sup[(size_t)NN * DD];   // support (gather operand), fp16
__device__ __half g_h[(size_t)NN * DD];     // hidden layer, fp16
__device__ __half g_w1t[DD * DD];           // W1^T fp16 ([n][k])
__device__ __half g_w2t[DD * DD];           // W2^T fp16
__device__ int    g_cursor[NN];             // per-node fill cursor == degree
__device__ int2   g_edges[(size_t)NN * CAP]; // (src, weight-as-half2-broadcast)

// ---------------------------------------------------------------------------
// Prep: zero cursors + convert/transpose both weight matrices to fp16.
// ---------------------------------------------------------------------------
__global__ void prep_kernel(const float* __restrict__ W1, const float* __restrict__ W2,
                            __half* __restrict__ W1t, __half* __restrict__ W2t,
                            int* __restrict__ cursor)
{
    int idx = blockIdx.x * blockDim.x + threadIdx.x;
    if (idx < NN) cursor[idx] = 0;
    if (idx < DD * DD) {
        int k = idx >> 7;
        int n = idx & 127;
        W1t[n * DD + k] = __float2half(W1[idx]);
        W2t[n * DD + k] = __float2half(W2[idx]);
    }
}

// ---------------------------------------------------------------------------
// HGEMM via mma.sync m16n8k16 (fp16 in, fp32 acc, fp16 out).
// out[m][n] = sum_k act(X[m][k]) * W[k][n],  Wt given as [n][k].
// BM=64, BN=128, K=128 staged in smem. 8 warps (2Mx4N), warp = m32 x n32.
// ---------------------------------------------------------------------------
#define GEMM_SMEM ((64 + 128) * 136 * 2)

template <typename InT, bool RELU>
__global__ __launch_bounds__(256) void hgemm_kernel(
    const InT* __restrict__ X, const __half* __restrict__ Wt,
    __half* __restrict__ out)
{
    extern __shared__ __align__(16) __half sh[];
    __half (*Ash)[136] = reinterpret_cast<__half(*)[136]>(sh);            // 64 x 136
    __half (*Bsh)[136] = reinterpret_cast<__half(*)[136]>(sh + 64 * 136); // 128 x 136

    const int tid = threadIdx.x;
    const int lane = tid & 31;
    const int wid = tid >> 5;
    const int block_row = blockIdx.x * 64;

    // ---- Load B: Wt [128][128] -> Bsh[n][k] ----
#pragma unroll
    for (int i = 0; i < 16; i++) {
        int idx = tid + i * 256;            // uint2 units (4 halfs)
        int n = idx >> 5;
        int c4 = (idx & 31) * 4;
        uint2 v = *(const uint2*)(Wt + n * DD + c4);
        *(uint2*)&Bsh[n][c4] = v;
    }

    // ---- Load A tile: 64 x 128, convert/relu -> Ash ----
    if constexpr (sizeof(InT) == 4) {
#pragma unroll
        for (int i = 0; i < 8; i++) {
            int idx = tid + i * 256;        // float4 units
            int r = idx >> 5;
            int c4 = (idx & 31) * 4;
            int gr = block_row + r;
            float4 v = make_float4(0.f, 0.f, 0.f, 0.f);
            if (gr < NN) v = *(const float4*)((const float*)X + (size_t)gr * DD + c4);
            if (RELU) {
                v.x = fmaxf(v.x, 0.f); v.y = fmaxf(v.y, 0.f);
                v.z = fmaxf(v.z, 0.f); v.w = fmaxf(v.w, 0.f);
            }
            __half2 h0 = __floats2half2_rn(v.x, v.y);
            __half2 h1 = __floats2half2_rn(v.z, v.w);
            uint2 pk;
            pk.x = *reinterpret_cast<uint*>(&h0);
            pk.y = *reinterpret_cast<uint*>(&h1);
            *(uint2*)&Ash[r][c4] = pk;
        }
    } else {
#pragma unroll
        for (int i = 0; i < 8; i++) {
            int idx = tid + i * 256;        // uint2 units (4 halfs)
            int r = idx >> 5;
            int c4 = (idx & 31) * 4;
            int gr = block_row + r;
            uint2 v = make_uint2(0u, 0u);
            if (gr < NN) v = *(const uint2*)((const __half*)X + (size_t)gr * DD + c4);
            if (RELU) {
                __half2 z = __float2half2_rn(0.f);
                __half2 a = __hmax2(*reinterpret_cast<__half2*>(&v.x), z);
                __half2 b = __hmax2(*reinterpret_cast<__half2*>(&v.y), z);
                v.x = *reinterpret_cast<uint*>(&a);
                v.y = *reinterpret_cast<uint*>(&b);
            }
            *(uint2*)&Ash[r][c4] = v;
        }
    }
    __syncthreads();

    // ---- Compute ----
    const int warp_m = (wid >> 2) * 32;   // 0 or 32
    const int warp_n = (wid & 3) * 32;    // 0,32,64,96
    const int gr = lane >> 2;             // group row / B col
    const int qc = lane & 3;              // quad id

    float acc[2][4][4];
#pragma unroll
    for (int mt = 0; mt < 2; mt++)
#pragma unroll
        for (int nt = 0; nt < 4; nt++)
#pragma unroll
            for (int j = 0; j < 4; j++) acc[mt][nt][j] = 0.f;

#pragma unroll
    for (int k0 = 0; k0 < DD; k0 += 16) {
        int kc = k0 + 2 * qc;
        uint a[2][4];
#pragma unroll
        for (int mt = 0; mt < 2; mt++) {
            int r0 = warp_m + mt * 16 + gr;
            a[mt][0] = *(const uint*)&Ash[r0][kc];
            a[mt][1] = *(const uint*)&Ash[r0 + 8][kc];
            a[mt][2] = *(const uint*)&Ash[r0][kc + 8];
            a[mt][3] = *(const uint*)&Ash[r0 + 8][kc + 8];
        }
#pragma unroll
        for (int nt = 0; nt < 4; nt++) {
            int n = warp_n + nt * 8 + gr;
            uint b0 = *(const uint*)&Bsh[n][kc];
            uint b1 = *(const uint*)&Bsh[n][kc + 8];
#pragma unroll
            for (int mt = 0; mt < 2; mt++) {
                asm volatile(
                    "mma.sync.aligned.m16n8k16.row.col.f32.f16.f16.f32 "
                    "{%0,%1,%2,%3}, {%4,%5,%6,%7}, {%8,%9}, {%0,%1,%2,%3};"
                    : "+f"(acc[mt][nt][0]), "+f"(acc[mt][nt][1]),
                      "+f"(acc[mt][nt][2]), "+f"(acc[mt][nt][3])
                    : "r"(a[mt][0]), "r"(a[mt][1]), "r"(a[mt][2]), "r"(a[mt][3]),
                      "r"(b0), "r"(b1));
            }
        }
    }

    // ---- Store (fp16) ----
#pragma unroll
    for (int mt = 0; mt < 2; mt++) {
        int r0 = block_row + warp_m + mt * 16 + gr;
#pragma unroll
        for (int nt = 0; nt < 4; nt++) {
            int col = warp_n + nt * 8 + 2 * qc;
            if (r0 < NN) {
                __half2 p = __floats2half2_rn(acc[mt][nt][0], acc[mt][nt][1]);
                *(__half2*)(out + (size_t)r0 * DD + col) = p;
            }
            if (r0 + 8 < NN) {
                __half2 p = __floats2half2_rn(acc[mt][nt][2], acc[mt][nt][3]);
                *(__half2*)(out + (size_t)(r0 + 8) * DD + col) = p;
            }
        }
    }
}

// ---------------------------------------------------------------------------
// Bucket fill: one edge per thread. Weight pre-converted to broadcast half2.
// edges[d*CAP + cursor[d]++] = (src, half2(w, w))
// ---------------------------------------------------------------------------
__global__ void fill_kernel(
    const int* __restrict__ src, const int* __restrict__ dst,
    const float* __restrict__ w, int* __restrict__ cursor,
    int2* __restrict__ edges, int nE)
{
    int e = blockIdx.x * blockDim.x + threadIdx.x;
    if (e >= nE) return;
    int d = __ldg(dst + e);
    int slot = atomicAdd(cursor + d, 1);
    __half2 w2 = __float2half2_rn(__ldg(w + e));
    edges[(size_t)d * CAP + slot] =
        make_int2(__ldg(src + e), (int)*reinterpret_cast<uint*>(&w2));
}

// ---------------------------------------------------------------------------
// Gather-aggregate: warp per node, 16 lanes per edge.
// Main: 16-edge waves (8 edges per half-warp, HFMA2 accumulate, fp32 flush).
// Tail: one padded 16-wave if rem>8, else one padded 8-wave (less L1 waste).
// ---------------------------------------------------------------------------
template <typename OutT>
__global__ __launch_bounds__(256) void gather_kernel(
    const __half* __restrict__ sup,
    const int2* __restrict__ edges,
    const int* __restrict__ cursor, const float* __restrict__ bias,
    OutT* __restrict__ out)
{
    int n = (int)((blockIdx.x * (unsigned)blockDim.x + threadIdx.x) >> 5);
    int lane = threadIdx.x & 31;
    if (n >= NN) return;

    const int half_id = lane >> 4;       // 0 or 1: which edge of the pair
    const int fl = lane & 15;            // feature slice: halfs [fl*8, fl*8+8)

    const int2* ebase = edges + (size_t)n * CAP + half_id;
    const int row_off = fl * 8;
    int deg = __ldg(cursor + n);

    float acc[8];
#pragma unroll
    for (int j = 0; j < 8; j++) acc[j] = 0.f;

    // ---- wave macro bodies (E = edges per half-warp this wave) ----
    auto wave = [&](int k, int nEdgesHalf) {
        __half2 w2[8];
        const __half* rp[8];
        for (int u = 0; u < nEdgesHalf; u++) {
            int2 p = __ldg(ebase + k + 2 * u);
            w2[u] = *reinterpret_cast<__half2*>(&p.y);
            rp[u] = sup + (size_t)p.x * DD + row_off;
        }
        uint4 v[8];
        for (int u = 0; u < nEdgesHalf; u++) v[u] = *(const uint4*)rp[u];

        __half2 hacc[4];
#pragma unroll
        for (int j = 0; j < 4; j++) hacc[j] = __float2half2_rn(0.f);
        for (int u = 0; u < nEdgesHalf; u++) {
            hacc[0] = __hfma2(w2[u], *reinterpret_cast<__half2*>(&v[u].x), hacc[0]);
            hacc[1] = __hfma2(w2[u], *reinterpret_cast<__half2*>(&v[u].y), hacc[1]);
            hacc[2] = __hfma2(w2[u], *reinterpret_cast<__half2*>(&v[u].z), hacc[2]);
            hacc[3] = __hfma2(w2[u], *reinterpret_cast<__half2*>(&v[u].w), hacc[3]);
        }
#pragma unroll
        for (int j = 0; j < 4; j++) {
            float2 f = __half22float2(hacc[j]);
            acc[2 * j + 0] += f.x;
            acc[2 * j + 1] += f.y;
        }
    };

    int k = 0;
    for (; k + 16 <= deg; k += 16) wave(k, 8);
    int rem = deg - k;                    // 0..15
    if (rem > 8)      wave(k, 8);         // padded 16-wave
    else if (rem > 0) wave(k, 4);         // padded 8-wave (half the L1 waste)

    // Fold the two half-warps (same feature slice, different edges).
#pragma unroll
    for (int j = 0; j < 8; j++)
        acc[j] += __shfl_xor_sync(0xffffffffu, acc[j], 16);

    if (lane < 16) {
        const float* bp = bias + row_off;
#pragma unroll
        for (int j = 0; j < 8; j++) acc[j] += __ldg(bp + j);

        if constexpr (sizeof(OutT) == 4) {
            float* op = (float*)out + (size_t)n * DD + row_off;
            *(float4*)(op) = make_float4(acc[0], acc[1], acc[2], acc[3]);
            *(float4*)(op + 4) = make_float4(acc[4], acc[5], acc[6], acc[7]);
        } else {
            __half2 h0 = __floats2half2_rn(acc[0], acc[1]);
            __half2 h1 = __floats2half2_rn(acc[2], acc[3]);
            __half2 h2 = __floats2half2_rn(acc[4], acc[5]);
            __half2 h3 = __floats2half2_rn(acc[6], acc[7]);
            uint4 pk;
            pk.x = *reinterpret_cast<uint*>(&h0);
            pk.y = *reinterpret_cast<uint*>(&h1);
            pk.z = *reinterpret_cast<uint*>(&h2);
            pk.w = *reinterpret_cast<uint*>(&h3);
            *(uint4*)((__half*)out + (size_t)n * DD + row_off) = pk;
        }
    }
}

// ---------------------------------------------------------------------------
// kernel_launch
// ---------------------------------------------------------------------------
extern "C" void kernel_launch(void* const* d_in, const int* in_sizes, int n_in,
                              void* d_out, int out_size)
{
    const float* features = (const float*)d_in[0];
    const int*   edge_src = (const int*)d_in[1];
    const int*   edge_dst = (const int*)d_in[2];
    const float* edge_w   = (const float*)d_in[3];
    const float* W1       = (const float*)d_in[4];
    const float* b1       = (const float*)d_in[5];
    const float* W2       = (const float*)d_in[6];
    const float* b2       = (const float*)d_in[7];
    float* out = (float*)d_out;

    const int nE = in_sizes[1];

    __half* sup;  cudaGetSymbolAddress((void**)&sup, g_sup);
    __half* h;    cudaGetSymbolAddress((void**)&h, g_h);
    __half* w1t;  cudaGetSymbolAddress((void**)&w1t, g_w1t);
    __half* w2t;  cudaGetSymbolAddress((void**)&w2t, g_w2t);
    int* cursor;  cudaGetSymbolAddress((void**)&cursor, g_cursor);
    int2* edges;  cudaGetSymbolAddress((void**)&edges, g_edges);

    cudaFuncSetAttribute(hgemm_kernel<float, false>,
                         cudaFuncAttributeMaxDynamicSharedMemorySize, GEMM_SMEM);
    cudaFuncSetAttribute(hgemm_kernel<__half, true>,
                         cudaFuncAttributeMaxDynamicSharedMemorySize, GEMM_SMEM);

    const int gemm_grid = (NN + 63) / 64;
    const int edge_grid = (nE + 255) / 256;
    const int prep_grid = (NN + 255) / 256;
    const int gather_grid = (NN * 32 + 255) / 256;

    // ---- Prep (zero cursors, convert weights) + bucket fill ----
    prep_kernel<<<prep_grid, 256>>>(W1, W2, w1t, w2t, cursor);
    fill_kernel<<<edge_grid, 256>>>(edge_src, edge_dst, edge_w, cursor, edges, nE);

    // ---- Layer 1: sup = X@W1 (fp16), h = bias1 + gather (fp16) ----
    hgemm_kernel<float, false><<<gemm_grid, 256, GEMM_SMEM>>>(features, w1t, sup);
    gather_kernel<__half><<<gather_grid, 256>>>(sup, edges, cursor, b1, h);

    // ---- Layer 2: sup = relu(h)@W2 (fp16), out = bias2 + gather (fp32) ----
    hgemm_kernel<__half, true><<<gemm_grid, 256, GEMM_SMEM>>>(h, w2t, sup);
    gather_kernel<float><<<gather_grid, 256>>>(sup, edges, cursor, b2, out);
}

// round 12
// speedup vs baseline: 1.0247x; 1.0247x over previous
#include <cuda_runtime.h>
#include <cuda_fp16.h>
#include <cuda_bf16.h>

#define NN 50000
#define DD 128
#define CAP 96           // bucket capacity per node; P(Poisson(32) >= 96) ~ 1e-18

typedef unsigned int uint;

// Scratch (no allocation allowed). g_edges is zero-initialized at module load;
// slots beyond each node's degree are NEVER written -> (src=0, w=0) padding.
__device__ __half g_sup[(size_t)NN * DD];   // support (gather operand), fp16
__device__ __half g_h[(size_t)NN * DD];     // hidden layer, fp16
__device__ __half g_w2t[DD * DD];           // W2^T fp16 ([n][k])
__device__ int    g_cursor[NN];             // per-node fill cursor == degree
__device__ int2   g_edges[(size_t)NN * CAP]; // (src, weight-as-half2-broadcast)

// ---------------------------------------------------------------------------
// Prep: zero cursors + convert/transpose W2 to fp16. (W1 is consumed fp32 by
// the layer-1 GEMM so the forked GEMM branch has no dependency on prep.)
// ---------------------------------------------------------------------------
__global__ void prep_kernel(const float* __restrict__ W2,
                            __half* __restrict__ W2t, int* __restrict__ cursor)
{
    int idx = blockIdx.x * blockDim.x + threadIdx.x;
    if (idx < NN) cursor[idx] = 0;
    if (idx < DD * DD) {
        int k = idx >> 7;
        int n = idx & 127;
        W2t[n * DD + k] = __float2half(W2[idx]);
    }
}

// ---------------------------------------------------------------------------
// Shared HGEMM core (Ash/Bsh staged, mma.sync m16n8k16, fp16 out).
// ---------------------------------------------------------------------------
#define GEMM_SMEM ((64 + 128) * 136 * 2)

__device__ __forceinline__ void hgemm_core(
    __half (*Ash)[136], __half (*Bsh)[136],
    int tid, int block_row, __half* __restrict__ out)
{
    const int lane = tid & 31;
    const int wid = tid >> 5;
    const int warp_m = (wid >> 2) * 32;
    const int warp_n = (wid & 3) * 32;
    const int gr = lane >> 2;
    const int qc = lane & 3;

    float acc[2][4][4];
#pragma unroll
    for (int mt = 0; mt < 2; mt++)
#pragma unroll
        for (int nt = 0; nt < 4; nt++)
#pragma unroll
            for (int j = 0; j < 4; j++) acc[mt][nt][j] = 0.f;

#pragma unroll
    for (int k0 = 0; k0 < DD; k0 += 16) {
        int kc = k0 + 2 * qc;
        uint a[2][4];
#pragma unroll
        for (int mt = 0; mt < 2; mt++) {
            int r0 = warp_m + mt * 16 + gr;
            a[mt][0] = *(const uint*)&Ash[r0][kc];
            a[mt][1] = *(const uint*)&Ash[r0 + 8][kc];
            a[mt][2] = *(const uint*)&Ash[r0][kc + 8];
            a[mt][3] = *(const uint*)&Ash[r0 + 8][kc + 8];
        }
#pragma unroll
        for (int nt = 0; nt < 4; nt++) {
            int n = warp_n + nt * 8 + gr;
            uint b0 = *(const uint*)&Bsh[n][kc];
            uint b1 = *(const uint*)&Bsh[n][kc + 8];
#pragma unroll
            for (int mt = 0; mt < 2; mt++) {
                asm volatile(
                    "mma.sync.aligned.m16n8k16.row.col.f32.f16.f16.f32 "
                    "{%0,%1,%2,%3}, {%4,%5,%6,%7}, {%8,%9}, {%0,%1,%2,%3};"
                    : "+f"(acc[mt][nt][0]), "+f"(acc[mt][nt][1]),
                      "+f"(acc[mt][nt][2]), "+f"(acc[mt][nt][3])
                    : "r"(a[mt][0]), "r"(a[mt][1]), "r"(a[mt][2]), "r"(a[mt][3]),
                      "r"(b0), "r"(b1));
            }
        }
    }

#pragma unroll
    for (int mt = 0; mt < 2; mt++) {
        int r0 = block_row + warp_m + mt * 16 + gr;
#pragma unroll
        for (int nt = 0; nt < 4; nt++) {
            int col = warp_n + nt * 8 + 2 * qc;
            if (r0 < NN) {
                __half2 p = __floats2half2_rn(acc[mt][nt][0], acc[mt][nt][1]);
                *(__half2*)(out + (size_t)r0 * DD + col) = p;
            }
            if (r0 + 8 < NN) {
                __half2 p = __floats2half2_rn(acc[mt][nt][2], acc[mt][nt][3]);
                *(__half2*)(out + (size_t)(r0 + 8) * DD + col) = p;
            }
        }
    }
}

// Layer 1: X fp32, W fp32 row-major [k][n] (transposed+converted in the load).
__global__ __launch_bounds__(256) void hgemm1_kernel(
    const float* __restrict__ X, const float* __restrict__ W,
    __half* __restrict__ out)
{
    extern __shared__ __align__(16) __half sh[];
    __half (*Ash)[136] = reinterpret_cast<__half(*)[136]>(sh);
    __half (*Bsh)[136] = reinterpret_cast<__half(*)[136]>(sh + 64 * 136);

    const int tid = threadIdx.x;
    const int block_row = blockIdx.x * 64;

    // B: fp32 W[k][n] -> Bsh[n][k], coalesced reads along n.
#pragma unroll
    for (int i = 0; i < 64; i++) {
        int idx = tid + i * 256;
        int k = idx >> 7;
        int n = idx & 127;
        Bsh[n][k] = __float2half(W[idx]);
    }
    // A: fp32 -> fp16
#pragma unroll
    for (int i = 0; i < 8; i++) {
        int idx = tid + i * 256;
        int r = idx >> 5;
        int c4 = (idx & 31) * 4;
        int gr = block_row + r;
        float4 v = make_float4(0.f, 0.f, 0.f, 0.f);
        if (gr < NN) v = *(const float4*)(X + (size_t)gr * DD + c4);
        __half2 h0 = __floats2half2_rn(v.x, v.y);
        __half2 h1 = __floats2half2_rn(v.z, v.w);
        uint2 pk;
        pk.x = *reinterpret_cast<uint*>(&h0);
        pk.y = *reinterpret_cast<uint*>(&h1);
        *(uint2*)&Ash[r][c4] = pk;
    }
    __syncthreads();
    hgemm_core(Ash, Bsh, tid, block_row, out);
}

// Layer 2: X fp16 (+ReLU), Wt fp16 [n][k].
__global__ __launch_bounds__(256) void hgemm2_kernel(
    const __half* __restrict__ X, const __half* __restrict__ Wt,
    __half* __restrict__ out)
{
    extern __shared__ __align__(16) __half sh[];
    __half (*Ash)[136] = reinterpret_cast<__half(*)[136]>(sh);
    __half (*Bsh)[136] = reinterpret_cast<__half(*)[136]>(sh + 64 * 136);

    const int tid = threadIdx.x;
    const int block_row = blockIdx.x * 64;

#pragma unroll
    for (int i = 0; i < 16; i++) {
        int idx = tid + i * 256;
        int n = idx >> 5;
        int c4 = (idx & 31) * 4;
        *(uint2*)&Bsh[n][c4] = *(const uint2*)(Wt + n * DD + c4);
    }
#pragma unroll
    for (int i = 0; i < 8; i++) {
        int idx = tid + i * 256;
        int r = idx >> 5;
        int c4 = (idx & 31) * 4;
        int gr = block_row + r;
        uint2 v = make_uint2(0u, 0u);
        if (gr < NN) v = *(const uint2*)(X + (size_t)gr * DD + c4);
        __half2 z = __float2half2_rn(0.f);
        __half2 a = __hmax2(*reinterpret_cast<__half2*>(&v.x), z);
        __half2 b = __hmax2(*reinterpret_cast<__half2*>(&v.y), z);
        v.x = *reinterpret_cast<uint*>(&a);
        v.y = *reinterpret_cast<uint*>(&b);
        *(uint2*)&Ash[r][c4] = v;
    }
    __syncthreads();
    hgemm_core(Ash, Bsh, tid, block_row, out);
}

// ---------------------------------------------------------------------------
// Bucket fill: one edge per thread. Weight pre-converted to broadcast half2.
// ---------------------------------------------------------------------------
__global__ void fill_kernel(
    const int* __restrict__ src, const int* __restrict__ dst,
    const float* __restrict__ w, int* __restrict__ cursor,
    int2* __restrict__ edges, int nE)
{
    int e = blockIdx.x * blockDim.x + threadIdx.x;
    if (e >= nE) return;
    int d = __ldg(dst + e);
    int slot = atomicAdd(cursor + d, 1);
    __half2 w2 = __float2half2_rn(__ldg(w + e));
    edges[(size_t)d * CAP + slot] =
        make_int2(__ldg(src + e), (int)*reinterpret_cast<uint*>(&w2));
}

// ---------------------------------------------------------------------------
// Gather-aggregate (R10 verbatim): warp per node, 16 lanes per edge,
// HFMA2 per-wave accumulation with fp32 flush.
// ---------------------------------------------------------------------------
template <typename OutT>
__global__ __launch_bounds__(256) void gather_kernel(
    const __half* __restrict__ sup,
    const int2* __restrict__ edges,
    const int* __restrict__ cursor, const float* __restrict__ bias,
    OutT* __restrict__ out)
{
    int n = (int)((blockIdx.x * (unsigned)blockDim.x + threadIdx.x) >> 5);
    int lane = threadIdx.x & 31;
    if (n >= NN) return;

    const int half_id = lane >> 4;
    const int fl = lane & 15;

    const int2* ebase = edges + (size_t)n * CAP + half_id;
    const int row_off = fl * 8;
    int deg = __ldg(cursor + n);

    float acc[8];
#pragma unroll
    for (int j = 0; j < 8; j++) acc[j] = 0.f;

    for (int k = 0; k < deg; k += 16) {
        __half2 w2[8];
        const __half* rp[8];
#pragma unroll
        for (int u = 0; u < 8; u++) {
            int2 p = __ldg(ebase + k + 2 * u);
            w2[u] = *reinterpret_cast<__half2*>(&p.y);
            rp[u] = sup + (size_t)p.x * DD + row_off;
        }
        uint4 v[8];
#pragma unroll
        for (int u = 0; u < 8; u++) v[u] = *(const uint4*)rp[u];

        __half2 hacc[4];
#pragma unroll
        for (int j = 0; j < 4; j++) hacc[j] = __float2half2_rn(0.f);
#pragma unroll
        for (int u = 0; u < 8; u++) {
            hacc[0] = __hfma2(w2[u], *reinterpret_cast<__half2*>(&v[u].x), hacc[0]);
            hacc[1] = __hfma2(w2[u], *reinterpret_cast<__half2*>(&v[u].y), hacc[1]);
            hacc[2] = __hfma2(w2[u], *reinterpret_cast<__half2*>(&v[u].z), hacc[2]);
            hacc[3] = __hfma2(w2[u], *reinterpret_cast<__half2*>(&v[u].w), hacc[3]);
        }
#pragma unroll
        for (int j = 0; j < 4; j++) {
            float2 f = __half22float2(hacc[j]);
            acc[2 * j + 0] += f.x;
            acc[2 * j + 1] += f.y;
        }
    }

#pragma unroll
    for (int j = 0; j < 8; j++)
        acc[j] += __shfl_xor_sync(0xffffffffu, acc[j], 16);

    if (lane < 16) {
        const float* bp = bias + row_off;
#pragma unroll
        for (int j = 0; j < 8; j++) acc[j] += __ldg(bp + j);

        if constexpr (sizeof(OutT) == 4) {
            float* op = (float*)out + (size_t)n * DD + row_off;
            *(float4*)(op) = make_float4(acc[0], acc[1], acc[2], acc[3]);
            *(float4*)(op + 4) = make_float4(acc[4], acc[5], acc[6], acc[7]);
        } else {
            __half2 h0 = __floats2half2_rn(acc[0], acc[1]);
            __half2 h1 = __floats2half2_rn(acc[2], acc[3]);
            __half2 h2 = __floats2half2_rn(acc[4], acc[5]);
            __half2 h3 = __floats2half2_rn(acc[6], acc[7]);
            uint4 pk;
            pk.x = *reinterpret_cast<uint*>(&h0);
            pk.y = *reinterpret_cast<uint*>(&h1);
            pk.z = *reinterpret_cast<uint*>(&h2);
            pk.w = *reinterpret_cast<uint*>(&h3);
            *(uint4*)((__half*)out + (size_t)n * DD + row_off) = pk;
        }
    }
}

// ---------------------------------------------------------------------------
// kernel_launch — graph fork/join: hgemm1 (reads only features+W1) runs on a
// side stream concurrently with prep+fill on the capture stream. Streams and
// events are created lazily on the first (uncaptured) correctness call; the
// captured work is identical every call.
// ---------------------------------------------------------------------------
extern "C" void kernel_launch(void* const* d_in, const int* in_sizes, int n_in,
                              void* d_out, int out_size)
{
    const float* features = (const float*)d_in[0];
    const int*   edge_src = (const int*)d_in[1];
    const int*   edge_dst = (const int*)d_in[2];
    const float* edge_w   = (const float*)d_in[3];
    const float* W1       = (const float*)d_in[4];
    const float* b1       = (const float*)d_in[5];
    const float* W2       = (const float*)d_in[6];
    const float* b2       = (const float*)d_in[7];
    float* out = (float*)d_out;

    const int nE = in_sizes[1];

    __half* sup;  cudaGetSymbolAddress((void**)&sup, g_sup);
    __half* h;    cudaGetSymbolAddress((void**)&h, g_h);
    __half* w2t;  cudaGetSymbolAddress((void**)&w2t, g_w2t);
    int* cursor;  cudaGetSymbolAddress((void**)&cursor, g_cursor);
    int2* edges;  cudaGetSymbolAddress((void**)&edges, g_edges);

    static cudaStream_t s2 = nullptr;
    static cudaEvent_t evFork = nullptr, evJoin = nullptr;
    if (s2 == nullptr) {
        cudaStreamCreateWithFlags(&s2, cudaStreamNonBlocking);
        cudaEventCreateWithFlags(&evFork, cudaEventDisableTiming);
        cudaEventCreateWithFlags(&evJoin, cudaEventDisableTiming);
        cudaFuncSetAttribute(hgemm1_kernel,
                             cudaFuncAttributeMaxDynamicSharedMemorySize, GEMM_SMEM);
        cudaFuncSetAttribute(hgemm2_kernel,
                             cudaFuncAttributeMaxDynamicSharedMemorySize, GEMM_SMEM);
    }

    const int gemm_grid = (NN + 63) / 64;
    const int edge_grid = (nE + 255) / 256;
    const int prep_grid = (NN + 255) / 256;
    const int gather_grid = (NN * 32 + 255) / 256;

    // ---- Fork: hgemm1 on s2, prep+fill on the capture (default) stream ----
    cudaEventRecord(evFork, 0);
    cudaStreamWaitEvent(s2, evFork, 0);

    hgemm1_kernel<<<gemm_grid, 256, GEMM_SMEM, s2>>>(features, W1, sup);
    prep_kernel<<<prep_grid, 256>>>(W2, w2t, cursor);
    fill_kernel<<<edge_grid, 256>>>(edge_src, edge_dst, edge_w, cursor, edges, nE);

    cudaEventRecord(evJoin, s2);
    cudaStreamWaitEvent(0, evJoin, 0);

    // ---- Join: gather1 -> gemm2 -> gather2 ----
    gather_kernel<__half><<<gather_grid, 256>>>(sup, edges, cursor, b1, h);
    hgemm2_kernel<<<gemm_grid, 256, GEMM_SMEM>>>(h, w2t, sup);
    gather_kernel<float><<<gather_grid, 256>>>(sup, edges, cursor, b2, out);
}

// round 13
// speedup vs baseline: 1.0630x; 1.0374x over previous
#include <cuda_runtime.h>
#include <cuda_fp16.h>
#include <cuda_bf16.h>

#define NN 50000
#define DD 128
#define CAP 96           // bucket capacity per node; P(Poisson(32) >= 96) ~ 1e-18

typedef unsigned int uint;

// Scratch (no allocation allowed). g_edges is zero-initialized at module load;
// slots beyond each node's degree are NEVER written, so they stay
// (src=0, w=half2(0,0)) forever -> safe zero-weight padding for the rounded-up
// gather loop (row 0 is L1-hot, padding loads generate no L2 traffic).
__device__ __half g_sup[(size_t)NN * DD];   // support (gather operand), fp16
__device__ __half g_h[(size_t)NN * DD];     // hidden layer, fp16
__device__ __half g_w1t[DD * DD];           // W1^T fp16 ([n][k])
__device__ __half g_w2t[DD * DD];           // W2^T fp16
__device__ int    g_cursor[NN];             // per-node fill cursor == degree
__device__ int2   g_edges[(size_t)NN * CAP]; // (src, weight-as-half2-broadcast)

// ---------------------------------------------------------------------------
// Prep: zero cursors + convert/transpose both weight matrices to fp16.
// ---------------------------------------------------------------------------
__global__ void prep_kernel(const float* __restrict__ W1, const float* __restrict__ W2,
                            __half* __restrict__ W1t, __half* __restrict__ W2t,
                            int* __restrict__ cursor)
{
    int idx = blockIdx.x * blockDim.x + threadIdx.x;
    if (idx < NN) cursor[idx] = 0;
    if (idx < DD * DD) {
        int k = idx >> 7;
        int n = idx & 127;
        W1t[n * DD + k] = __float2half(W1[idx]);
        W2t[n * DD + k] = __float2half(W2[idx]);
    }
}

// ---------------------------------------------------------------------------
// HGEMM via mma.sync m16n8k16 (fp16 in, fp32 acc, fp16 out). R10 verbatim.
// out[m][n] = sum_k act(X[m][k]) * W[k][n],  Wt given as [n][k].
// BM=64, BN=128, K=128 staged in smem. 8 warps (2Mx4N), warp = m32 x n32.
// ---------------------------------------------------------------------------
#define GEMM_SMEM ((64 + 128) * 136 * 2)

template <typename InT, bool RELU>
__global__ __launch_bounds__(256) void hgemm_kernel(
    const InT* __restrict__ X, const __half* __restrict__ Wt,
    __half* __restrict__ out)
{
    extern __shared__ __align__(16) __half sh[];
    __half (*Ash)[136] = reinterpret_cast<__half(*)[136]>(sh);            // 64 x 136
    __half (*Bsh)[136] = reinterpret_cast<__half(*)[136]>(sh + 64 * 136); // 128 x 136

    const int tid = threadIdx.x;
    const int lane = tid & 31;
    const int wid = tid >> 5;
    const int block_row = blockIdx.x * 64;

    // ---- Load B: Wt [128][128] -> Bsh[n][k] ----
#pragma unroll
    for (int i = 0; i < 16; i++) {
        int idx = tid + i * 256;            // uint2 units (4 halfs)
        int n = idx >> 5;
        int c4 = (idx & 31) * 4;
        uint2 v = *(const uint2*)(Wt + n * DD + c4);
        *(uint2*)&Bsh[n][c4] = v;
    }

    // ---- Load A tile: 64 x 128, convert/relu -> Ash ----
    if constexpr (sizeof(InT) == 4) {
#pragma unroll
        for (int i = 0; i < 8; i++) {
            int idx = tid + i * 256;        // float4 units
            int r = idx >> 5;
            int c4 = (idx & 31) * 4;
            int gr = block_row + r;
            float4 v = make_float4(0.f, 0.f, 0.f, 0.f);
            if (gr < NN) v = *(const float4*)((const float*)X + (size_t)gr * DD + c4);
            if (RELU) {
                v.x = fmaxf(v.x, 0.f); v.y = fmaxf(v.y, 0.f);
                v.z = fmaxf(v.z, 0.f); v.w = fmaxf(v.w, 0.f);
            }
            __half2 h0 = __floats2half2_rn(v.x, v.y);
            __half2 h1 = __floats2half2_rn(v.z, v.w);
            uint2 pk;
            pk.x = *reinterpret_cast<uint*>(&h0);
            pk.y = *reinterpret_cast<uint*>(&h1);
            *(uint2*)&Ash[r][c4] = pk;
        }
    } else {
#pragma unroll
        for (int i = 0; i < 8; i++) {
            int idx = tid + i * 256;        // uint2 units (4 halfs)
            int r = idx >> 5;
            int c4 = (idx & 31) * 4;
            int gr = block_row + r;
            uint2 v = make_uint2(0u, 0u);
            if (gr < NN) v = *(const uint2*)((const __half*)X + (size_t)gr * DD + c4);
            if (RELU) {
                __half2 z = __float2half2_rn(0.f);
                __half2 a = __hmax2(*reinterpret_cast<__half2*>(&v.x), z);
                __half2 b = __hmax2(*reinterpret_cast<__half2*>(&v.y), z);
                v.x = *reinterpret_cast<uint*>(&a);
                v.y = *reinterpret_cast<uint*>(&b);
            }
            *(uint2*)&Ash[r][c4] = v;
        }
    }
    __syncthreads();

    // ---- Compute ----
    const int warp_m = (wid >> 2) * 32;   // 0 or 32
    const int warp_n = (wid & 3) * 32;    // 0,32,64,96
    const int gr = lane >> 2;             // group row / B col
    const int qc = lane & 3;              // quad id

    float acc[2][4][4];
#pragma unroll
    for (int mt = 0; mt < 2; mt++)
#pragma unroll
        for (int nt = 0; nt < 4; nt++)
#pragma unroll
            for (int j = 0; j < 4; j++) acc[mt][nt][j] = 0.f;

#pragma unroll
    for (int k0 = 0; k0 < DD; k0 += 16) {
        int kc = k0 + 2 * qc;
        uint a[2][4];
#pragma unroll
        for (int mt = 0; mt < 2; mt++) {
            int r0 = warp_m + mt * 16 + gr;
            a[mt][0] = *(const uint*)&Ash[r0][kc];
            a[mt][1] = *(const uint*)&Ash[r0 + 8][kc];
            a[mt][2] = *(const uint*)&Ash[r0][kc + 8];
            a[mt][3] = *(const uint*)&Ash[r0 + 8][kc + 8];
        }
#pragma unroll
        for (int nt = 0; nt < 4; nt++) {
            int n = warp_n + nt * 8 + gr;
            uint b0 = *(const uint*)&Bsh[n][kc];
            uint b1 = *(const uint*)&Bsh[n][kc + 8];
#pragma unroll
            for (int mt = 0; mt < 2; mt++) {
                asm volatile(
                    "mma.sync.aligned.m16n8k16.row.col.f32.f16.f16.f32 "
                    "{%0,%1,%2,%3}, {%4,%5,%6,%7}, {%8,%9}, {%0,%1,%2,%3};"
                    : "+f"(acc[mt][nt][0]), "+f"(acc[mt][nt][1]),
                      "+f"(acc[mt][nt][2]), "+f"(acc[mt][nt][3])
                    : "r"(a[mt][0]), "r"(a[mt][1]), "r"(a[mt][2]), "r"(a[mt][3]),
                      "r"(b0), "r"(b1));
            }
        }
    }

    // ---- Store (fp16) ----
#pragma unroll
    for (int mt = 0; mt < 2; mt++) {
        int r0 = block_row + warp_m + mt * 16 + gr;
#pragma unroll
        for (int nt = 0; nt < 4; nt++) {
            int col = warp_n + nt * 8 + 2 * qc;
            if (r0 < NN) {
                __half2 p = __floats2half2_rn(acc[mt][nt][0], acc[mt][nt][1]);
                *(__half2*)(out + (size_t)r0 * DD + col) = p;
            }
            if (r0 + 8 < NN) {
                __half2 p = __floats2half2_rn(acc[mt][nt][2], acc[mt][nt][3]);
                *(__half2*)(out + (size_t)(r0 + 8) * DD + col) = p;
            }
        }
    }
}

// ---------------------------------------------------------------------------
// Bucket fill: one edge per thread. Weight pre-converted to broadcast half2.
// edges[d*CAP + cursor[d]++] = (src, half2(w, w))
// ---------------------------------------------------------------------------
__global__ void fill_kernel(
    const int* __restrict__ src, const int* __restrict__ dst,
    const float* __restrict__ w, int* __restrict__ cursor,
    int2* __restrict__ edges, int nE)
{
    int e = blockIdx.x * blockDim.x + threadIdx.x;
    if (e >= nE) return;
    int d = __ldg(dst + e);
    int slot = atomicAdd(cursor + d, 1);
    __half2 w2 = __float2half2_rn(__ldg(w + e));
    edges[(size_t)d * CAP + slot] =
        make_int2(__ldg(src + e), (int)*reinterpret_cast<uint*>(&w2));
}

// ---------------------------------------------------------------------------
// Gather-aggregate (R10 verbatim): warp per node, 16 lanes per edge,
// HFMA2 per-wave accumulation with fp32 flush.
// ---------------------------------------------------------------------------
template <typename OutT>
__global__ __launch_bounds__(256) void gather_kernel(
    const __half* __restrict__ sup,
    const int2* __restrict__ edges,
    const int* __restrict__ cursor, const float* __restrict__ bias,
    OutT* __restrict__ out)
{
    int n = (int)((blockIdx.x * (unsigned)blockDim.x + threadIdx.x) >> 5);
    int lane = threadIdx.x & 31;
    if (n >= NN) return;

    const int half_id = lane >> 4;
    const int fl = lane & 15;

    const int2* ebase = edges + (size_t)n * CAP + half_id;
    const int row_off = fl * 8;
    int deg = __ldg(cursor + n);

    float acc[8];
#pragma unroll
    for (int j = 0; j < 8; j++) acc[j] = 0.f;

    for (int k = 0; k < deg; k += 16) {
        __half2 w2[8];
        const __half* rp[8];
#pragma unroll
        for (int u = 0; u < 8; u++) {
            int2 p = __ldg(ebase + k + 2 * u);
            w2[u] = *reinterpret_cast<__half2*>(&p.y);
            rp[u] = sup + (size_t)p.x * DD + row_off;
        }
        uint4 v[8];
#pragma unroll
        for (int u = 0; u < 8; u++) v[u] = *(const uint4*)rp[u];

        __half2 hacc[4];
#pragma unroll
        for (int j = 0; j < 4; j++) hacc[j] = __float2half2_rn(0.f);
#pragma unroll
        for (int u = 0; u < 8; u++) {
            hacc[0] = __hfma2(w2[u], *reinterpret_cast<__half2*>(&v[u].x), hacc[0]);
            hacc[1] = __hfma2(w2[u], *reinterpret_cast<__half2*>(&v[u].y), hacc[1]);
            hacc[2] = __hfma2(w2[u], *reinterpret_cast<__half2*>(&v[u].z), hacc[2]);
            hacc[3] = __hfma2(w2[u], *reinterpret_cast<__half2*>(&v[u].w), hacc[3]);
        }
#pragma unroll
        for (int j = 0; j < 4; j++) {
            float2 f = __half22float2(hacc[j]);
            acc[2 * j + 0] += f.x;
            acc[2 * j + 1] += f.y;
        }
    }

#pragma unroll
    for (int j = 0; j < 8; j++)
        acc[j] += __shfl_xor_sync(0xffffffffu, acc[j], 16);

    if (lane < 16) {
        const float* bp = bias + row_off;
#pragma unroll
        for (int j = 0; j < 8; j++) acc[j] += __ldg(bp + j);

        if constexpr (sizeof(OutT) == 4) {
            float* op = (float*)out + (size_t)n * DD + row_off;
            *(float4*)(op) = make_float4(acc[0], acc[1], acc[2], acc[3]);
            *(float4*)(op + 4) = make_float4(acc[4], acc[5], acc[6], acc[7]);
        } else {
            __half2 h0 = __floats2half2_rn(acc[0], acc[1]);
            __half2 h1 = __floats2half2_rn(acc[2], acc[3]);
            __half2 h2 = __floats2half2_rn(acc[4], acc[5]);
            __half2 h3 = __floats2half2_rn(acc[6], acc[7]);
            uint4 pk;
            pk.x = *reinterpret_cast<uint*>(&h0);
            pk.y = *reinterpret_cast<uint*>(&h1);
            pk.z = *reinterpret_cast<uint*>(&h2);
            pk.w = *reinterpret_cast<uint*>(&h3);
            *(uint4*)((__half*)out + (size_t)n * DD + row_off) = pk;
        }
    }
}

// ---------------------------------------------------------------------------
// kernel_launch — fork AFTER prep: gemm1 (reads w1t written by prep) runs on
// s2 concurrently with fill on the capture stream. All kernels are the R10
// (130.1 us) binaries; only the stream structure differs. Lazy stream/event
// creation happens on the first, uncaptured call.
// ---------------------------------------------------------------------------
extern "C" void kernel_launch(void* const* d_in, const int* in_sizes, int n_in,
                              void* d_out, int out_size)
{
    const float* features = (const float*)d_in[0];
    const int*   edge_src = (const int*)d_in[1];
    const int*   edge_dst = (const int*)d_in[2];
    const float* edge_w   = (const float*)d_in[3];
    const float* W1       = (const float*)d_in[4];
    const float* b1       = (const float*)d_in[5];
    const float* W2       = (const float*)d_in[6];
    const float* b2       = (const float*)d_in[7];
    float* out = (float*)d_out;

    const int nE = in_sizes[1];

    __half* sup;  cudaGetSymbolAddress((void**)&sup, g_sup);
    __half* h;    cudaGetSymbolAddress((void**)&h, g_h);
    __half* w1t;  cudaGetSymbolAddress((void**)&w1t, g_w1t);
    __half* w2t;  cudaGetSymbolAddress((void**)&w2t, g_w2t);
    int* cursor;  cudaGetSymbolAddress((void**)&cursor, g_cursor);
    int2* edges;  cudaGetSymbolAddress((void**)&edges, g_edges);

    static cudaStream_t s2 = nullptr;
    static cudaEvent_t evPrep = nullptr, evJoin = nullptr;
    if (s2 == nullptr) {
        cudaStreamCreateWithFlags(&s2, cudaStreamNonBlocking);
        cudaEventCreateWithFlags(&evPrep, cudaEventDisableTiming);
        cudaEventCreateWithFlags(&evJoin, cudaEventDisableTiming);
        cudaFuncSetAttribute(hgemm_kernel<float, false>,
                             cudaFuncAttributeMaxDynamicSharedMemorySize, GEMM_SMEM);
        cudaFuncSetAttribute(hgemm_kernel<__half, true>,
                             cudaFuncAttributeMaxDynamicSharedMemorySize, GEMM_SMEM);
    }

    const int gemm_grid = (NN + 63) / 64;
    const int edge_grid = (nE + 255) / 256;
    const int prep_grid = (NN + 255) / 256;
    const int gather_grid = (NN * 32 + 255) / 256;

    // ---- prep on capture stream; fork gemm1 (depends on prep) onto s2 ----
    prep_kernel<<<prep_grid, 256>>>(W1, W2, w1t, w2t, cursor);
    cudaEventRecord(evPrep, 0);
    cudaStreamWaitEvent(s2, evPrep, 0);

    hgemm_kernel<float, false><<<gemm_grid, 256, GEMM_SMEM, s2>>>(features, w1t, sup);
    fill_kernel<<<edge_grid, 256>>>(edge_src, edge_dst, edge_w, cursor, edges, nE);

    cudaEventRecord(evJoin, s2);
    cudaStreamWaitEvent(0, evJoin, 0);

    // ---- Join: gather1 -> gemm2 -> gather2 ----
    gather_kernel<__half><<<gather_grid, 256>>>(sup, edges, cursor, b1, h);
    hgemm_kernel<__half, true><<<gemm_grid, 256, GEMM_SMEM>>>(h, w2t, sup);
    gather_kernel<float><<<gather_grid, 256>>>(sup, edges, cursor, b2, out);
}